// round 6
// baseline (speedup 1.0000x reference)
#include <cuda_runtime.h>

#define BATCH 4
#define C 256
#define H 256
#define W 256
#define S 8
#define HP 32
#define WP 32
#define N 1024     // HP*WP tokens
#define KC 32      // key channels

typedef unsigned int uint;

// ---------------- device scratch (no allocs allowed) ----------------
__device__ float g_xf[BATCH * C * N];        // pooled features  [b][c][n]   4 MB
__device__ float g_q[BATCH * KC * N];        // q                [b][k][n]
__device__ float g_k[BATCH * KC * N];        // k                [b][k][n]
__device__ float g_v[BATCH * C * N];         // v (tf32-rounded) [b][c][n]   4 MB
__device__ float g_attn[BATCH * N * N];      // probs (tf32-rnd) [b][n][m]  16 MB
__device__ float g_out[BATCH * C * N];       // attn output      [b][c][n]   4 MB

__device__ __forceinline__ float to_tf32(float x) {
    float r; asm("cvt.rna.tf32.f32 %0, %1;" : "=f"(r) : "f"(x)); return r;
}

__device__ __forceinline__ void mma_tf32(float* d, const uint* a, const uint* b) {
    asm volatile(
        "mma.sync.aligned.m16n8k8.row.col.f32.tf32.tf32.f32 "
        "{%0,%1,%2,%3}, {%4,%5,%6,%7}, {%8,%9}, {%0,%1,%2,%3};"
        : "+f"(d[0]), "+f"(d[1]), "+f"(d[2]), "+f"(d[3])
        : "r"(a[0]), "r"(a[1]), "r"(a[2]), "r"(a[3]), "r"(b[0]), "r"(b[1]));
}

__device__ __forceinline__ void cp16(uint smem_addr, const void* gptr) {
    asm volatile("cp.async.ca.shared.global [%0], [%1], 16;"
                 :: "r"(smem_addr), "l"(gptr));
}

// FMA-pipe exp (avoids MUFU serialization): exp(x) = 2^(x*log2e),
// round + deg-5 Taylor of 2^f on f in [-0.5,0.5] + exponent-bit ldexp.
__device__ __forceinline__ float fast_expf(float x) {
    x = fmaxf(x, -80.0f);                       // keep 2^n in normal range
    float y = x * 1.4426950408889634f;
    float z = y + 12582912.0f;                  // round-to-nearest via magic
    int   e = __float_as_int(z);                // low bits hold round(y)
    float n = z - 12582912.0f;
    float f = y - n;
    float p = 0.0013333558146428443f;
    p = fmaf(p, f, 0.009618129107628477f);
    p = fmaf(p, f, 0.05550410866482158f);
    p = fmaf(p, f, 0.2402265069591007f);
    p = fmaf(p, f, 0.6931471805599453f);
    p = fmaf(p, f, 1.0f);
    return __int_as_float(__float_as_int(p) + (e << 23));
}

// ---------------- kernel 1: 8x8 avg pool ----------------
__global__ void avgpool_kernel(const float* __restrict__ f) {
    int idx = blockIdx.x * blockDim.x + threadIdx.x;   // over BATCH*C*N
    int n  = idx & (N - 1);
    int bc = idx >> 10;
    int wp = n & (WP - 1);
    int hp = n >> 5;
    const float* src = f + ((size_t)bc * H + (size_t)hp * S) * W + (size_t)wp * S;
    float s = 0.f;
#pragma unroll
    for (int r = 0; r < S; r++) {
        float4 a = *(const float4*)(src + (size_t)r * W);
        float4 b = *(const float4*)(src + (size_t)r * W + 4);
        s += a.x + a.y + a.z + a.w + b.x + b.y + b.z + b.w;
    }
    g_xf[idx] = s * (1.f / 64.f);
}

// ---------------- kernel 2: q/k/v 1x1 convs (32-row register blocking) ----------------
// grid: (n_tiles=8, row_groups=10, batch=4), block 128
__global__ void qkv_kernel(const float* __restrict__ qw, const float* __restrict__ qb,
                           const float* __restrict__ kw, const float* __restrict__ kb,
                           const float* __restrict__ vw, const float* __restrict__ vb) {
    __shared__ __align__(16) float wsh[C][32];   // transposed: wsh[c][r]
    __shared__ float bsh[32];
    int b = blockIdx.z;
    int g = blockIdx.y;
    int n = blockIdx.x * 128 + threadIdx.x;

    const float* wsrc;
    const float* bsrc;
    float* dst;
    int r0;
    bool round_v;
    if (g == 0)      { wsrc = qw; bsrc = qb; dst = g_q + (size_t)b * KC * N; r0 = 0; round_v = false; }
    else if (g == 1) { wsrc = kw; bsrc = kb; dst = g_k + (size_t)b * KC * N; r0 = 0; round_v = false; }
    else             { wsrc = vw; bsrc = vb; dst = g_v + (size_t)b * C * N;  r0 = (g - 2) * 32; round_v = true; }

    for (int i = threadIdx.x; i < 32 * C; i += 128) {
        int r = i & 31, c = i >> 5;
        wsh[c][r] = wsrc[(size_t)(r0 + r) * C + c];
    }
    if (threadIdx.x < 32) bsh[threadIdx.x] = bsrc[r0 + threadIdx.x];
    __syncthreads();

    const float* xf = g_xf + (size_t)b * C * N + n;
    float acc[32];
#pragma unroll
    for (int r = 0; r < 32; r++) acc[r] = 0.f;

#pragma unroll 2
    for (int c = 0; c < C; c++) {
        float x = __ldg(xf + (size_t)c * N);
        const float4* wr = (const float4*)&wsh[c][0];
#pragma unroll
        for (int j = 0; j < 8; j++) {
            float4 w = wr[j];
            acc[4 * j + 0] = fmaf(w.x, x, acc[4 * j + 0]);
            acc[4 * j + 1] = fmaf(w.y, x, acc[4 * j + 1]);
            acc[4 * j + 2] = fmaf(w.z, x, acc[4 * j + 2]);
            acc[4 * j + 3] = fmaf(w.w, x, acc[4 * j + 3]);
        }
    }
#pragma unroll
    for (int r = 0; r < 32; r++) {
        float o = acc[r] + bsh[r];
        dst[(size_t)(r0 + r) * N + n] = round_v ? to_tf32(o) : o;
    }
}

// ---------------- kernel 3: energy + softmax (FMA-pipe exp, tf32-rounded store) ----------------
#define QT 8   // query rows per block
__global__ void attn_prob_kernel() {
    int b  = blockIdx.y;
    int n0 = blockIdx.x * QT;
    int tid  = threadIdx.x;
    int lane = tid & 31, wid = tid >> 5;

    __shared__ float qsh[QT][KC];
    __shared__ float red_m[QT][8];
    __shared__ float red_s[QT][8];

    {
        int r = tid >> 5, k = tid & 31;
        qsh[r][k] = g_q[((size_t)b * KC + k) * N + (n0 + r)];
    }
    __syncthreads();

    float e[QT][4];
#pragma unroll
    for (int r = 0; r < QT; r++)
#pragma unroll
        for (int j = 0; j < 4; j++) e[r][j] = 0.f;

    const float* Kp = g_k + (size_t)b * KC * N;
#pragma unroll 4
    for (int k = 0; k < KC; k++) {
        float kv0 = Kp[(size_t)k * N + tid];
        float kv1 = Kp[(size_t)k * N + tid + 256];
        float kv2 = Kp[(size_t)k * N + tid + 512];
        float kv3 = Kp[(size_t)k * N + tid + 768];
#pragma unroll
        for (int r = 0; r < QT; r++) {
            float qv = qsh[r][k];
            e[r][0] = fmaf(qv, kv0, e[r][0]);
            e[r][1] = fmaf(qv, kv1, e[r][1]);
            e[r][2] = fmaf(qv, kv2, e[r][2]);
            e[r][3] = fmaf(qv, kv3, e[r][3]);
        }
    }

    const float scale = 0.17677669529663687f;   // 32^-0.5
#pragma unroll
    for (int r = 0; r < QT; r++) {
#pragma unroll
        for (int j = 0; j < 4; j++) e[r][j] *= scale;
        float lm = fmaxf(fmaxf(e[r][0], e[r][1]), fmaxf(e[r][2], e[r][3]));
#pragma unroll
        for (int o = 16; o > 0; o >>= 1) lm = fmaxf(lm, __shfl_xor_sync(0xFFFFFFFFu, lm, o));
        if (lane == 0) red_m[r][wid] = lm;
    }
    __syncthreads();

#pragma unroll
    for (int r = 0; r < QT; r++) {
        float m2 = red_m[r][0];
#pragma unroll
        for (int w = 1; w < 8; w++) m2 = fmaxf(m2, red_m[r][w]);
        float ls = 0.f;
#pragma unroll
        for (int j = 0; j < 4; j++) { e[r][j] = fast_expf(e[r][j] - m2); ls += e[r][j]; }
#pragma unroll
        for (int o = 16; o > 0; o >>= 1) ls += __shfl_xor_sync(0xFFFFFFFFu, ls, o);
        if (lane == 0) red_s[r][wid] = ls;
    }
    __syncthreads();

    float* P = g_attn + (size_t)b * N * N;
#pragma unroll
    for (int r = 0; r < QT; r++) {
        float s2 = red_s[r][0];
#pragma unroll
        for (int w = 1; w < 8; w++) s2 += red_s[r][w];
        float inv = 1.f / s2;
#pragma unroll
        for (int j = 0; j < 4; j++)
            P[(size_t)(n0 + r) * N + tid + j * 256] = to_tf32(e[r][j] * inv);
    }
}

// ---------------- kernel 4: out = v @ attn^T via tf32 HMMA + cp.async pipeline ----------------
// out[b][c][n] = sum_m v[b][c][m] * attn[b][n][m]
// block: 256 thr = 8 warps (2c x 4n), block tile 64(c) x 64(n), warp tile 32x16, k-chunk 32, 2-stage.
#define GBM 64
#define GBN 64
#define GBK 32
#define LDP 36   // smem row stride (words): bank = lane for fragment loads -> conflict-free
#define NCHUNK (N / GBK)
__global__ void out_gemm_kernel() {
    int b  = blockIdx.z;
    int c0 = blockIdx.y * GBM;
    int n0 = blockIdx.x * GBN;
    __shared__ __align__(16) uint Vs[2][GBM * LDP];
    __shared__ __align__(16) uint Ps[2][GBN * LDP];

    int tid  = threadIdx.x;      // 0..255
    int lane = tid & 31, wid = tid >> 5;
    int wm = (wid & 1) * 32;     // warp c offset
    int wn = (wid >> 1) * 16;    // warp n offset (0,16,32,48)

    const uint* V = (const uint*)g_v    + (size_t)b * C * N;
    const uint* P = (const uint*)g_attn + (size_t)b * N * N;

    // copy slots: idx = tid + i*256 -> row = idx>>3 (0..63), f4 = (idx&7)*4
    int crow = tid >> 3;          // 0..31
    int cf4  = (tid & 7) * 4;

    float acc[2][2][4];
#pragma unroll
    for (int am = 0; am < 2; am++)
#pragma unroll
        for (int an = 0; an < 2; an++)
#pragma unroll
            for (int j = 0; j < 4; j++) acc[am][an][j] = 0.f;

    int r4  = lane >> 2;         // 0..7
    int q4  = lane & 3;          // 0..3

    // stage-0 prefetch
    {
#pragma unroll
        for (int i = 0; i < 2; i++) {
            int row = crow + i * 32;
            cp16((uint)__cvta_generic_to_shared(&Vs[0][row * LDP + cf4]),
                 V + (size_t)(c0 + row) * N + cf4);
            cp16((uint)__cvta_generic_to_shared(&Ps[0][row * LDP + cf4]),
                 P + (size_t)(n0 + row) * N + cf4);
        }
        asm volatile("cp.async.commit_group;");
    }

    for (int ch = 0; ch < NCHUNK; ch++) {
        int s = ch & 1;
        if (ch + 1 < NCHUNK) {
            int m1 = (ch + 1) * GBK;
#pragma unroll
            for (int i = 0; i < 2; i++) {
                int row = crow + i * 32;
                cp16((uint)__cvta_generic_to_shared(&Vs[s ^ 1][row * LDP + cf4]),
                     V + (size_t)(c0 + row) * N + m1 + cf4);
                cp16((uint)__cvta_generic_to_shared(&Ps[s ^ 1][row * LDP + cf4]),
                     P + (size_t)(n0 + row) * N + m1 + cf4);
            }
            asm volatile("cp.async.commit_group;");
            asm volatile("cp.async.wait_group 1;");
        } else {
            asm volatile("cp.async.wait_group 0;");
        }
        __syncthreads();

        const uint* Vss = Vs[s];
        const uint* Pss = Ps[s];
#pragma unroll
        for (int k8 = 0; k8 < GBK; k8 += 8) {
            uint a[2][4], bb[2][2];
#pragma unroll
            for (int am = 0; am < 2; am++) {
                int base = (wm + am * 16 + r4) * LDP + k8 + q4;
                a[am][0] = Vss[base];
                a[am][1] = Vss[base + 8 * LDP];
                a[am][2] = Vss[base + 4];
                a[am][3] = Vss[base + 8 * LDP + 4];
            }
#pragma unroll
            for (int an = 0; an < 2; an++) {
                int base = (wn + an * 8 + r4) * LDP + k8 + q4;
                bb[an][0] = Pss[base];
                bb[an][1] = Pss[base + 4];
            }
#pragma unroll
            for (int am = 0; am < 2; am++)
#pragma unroll
                for (int an = 0; an < 2; an++)
                    mma_tf32(acc[am][an], a[am], bb[an]);
        }
        __syncthreads();
    }

    float* O = g_out + (size_t)b * C * N;
    int cc = (lane & 3) * 2;
#pragma unroll
    for (int am = 0; am < 2; am++)
#pragma unroll
        for (int an = 0; an < 2; an++) {
            int cr = c0 + wm + am * 16 + r4;
            int ncol = n0 + wn + an * 8 + cc;
            float2 lo; lo.x = acc[am][an][0]; lo.y = acc[am][an][1];
            float2 hi; hi.x = acc[am][an][2]; hi.y = acc[am][an][3];
            *(float2*)(O + (size_t)cr * N + ncol)       = lo;
            *(float2*)(O + (size_t)(cr + 8) * N + ncol) = hi;
        }
}

// ---------------- kernel 5: nearest 8x upsample + residual ----------------
__global__ void upsample_add_kernel(const float* __restrict__ f, float* __restrict__ out) {
    size_t idx = (size_t)blockIdx.x * blockDim.x + threadIdx.x;  // over B*C*H*W/4
    int w4 = (int)(idx & 63);            // W/4 = 64
    int h  = (int)((idx >> 6) & 255);
    size_t bc = idx >> 14;
    int hp = h >> 3;
    int wp = w4 >> 1;                    // (w4*4)/8
    float s = g_out[bc * N + (size_t)hp * WP + wp];
    float4 a = ((const float4*)f)[idx];
    a.x += s; a.y += s; a.z += s; a.w += s;
    ((float4*)out)[idx] = a;
}

// ---------------- launch ----------------
extern "C" void kernel_launch(void* const* d_in, const int* in_sizes, int n_in,
                              void* d_out, int out_size) {
    const float* f  = (const float*)d_in[0];
    const float* qw = (const float*)d_in[1];
    const float* qb = (const float*)d_in[2];
    const float* kw = (const float*)d_in[3];
    const float* kb = (const float*)d_in[4];
    const float* vw = (const float*)d_in[5];
    const float* vb = (const float*)d_in[6];
    float* out = (float*)d_out;

    avgpool_kernel<<<(BATCH * C * N) / 256, 256>>>(f);
    qkv_kernel<<<dim3(8, 10, BATCH), 128>>>(qw, qb, kw, kb, vw, vb);
    attn_prob_kernel<<<dim3(N / QT, BATCH), 256>>>();
    out_gemm_kernel<<<dim3(N / GBN, C / GBM, BATCH), 256>>>();
    upsample_add_kernel<<<(BATCH * C * H * (W / 4)) / 256, 256>>>(f, out);
}

// round 7
// speedup vs baseline: 1.1160x; 1.1160x over previous
#include <cuda_runtime.h>

#define BATCH 4
#define C 256
#define H 256
#define W 256
#define S 8
#define HP 32
#define WP 32
#define N 1024     // HP*WP tokens
#define KC 32      // key channels

typedef unsigned int uint;

// ---------------- device scratch (no allocs allowed) ----------------
__device__ float g_xf[BATCH * C * N];        // pooled features  [b][c][n]   4 MB
__device__ float g_q[BATCH * KC * N];        // q                [b][k][n]
__device__ float g_k[BATCH * KC * N];        // k                [b][k][n]
__device__ float g_v[BATCH * C * N];         // v (tf32-rounded) [b][c][n]   4 MB
__device__ float g_attn[BATCH * N * N];      // probs (tf32-rnd) [b][n][m]  16 MB
__device__ float g_out[BATCH * C * N];       // attn output      [b][c][n]   4 MB

__device__ __forceinline__ float to_tf32(float x) {
    float r; asm("cvt.rna.tf32.f32 %0, %1;" : "=f"(r) : "f"(x)); return r;
}

__device__ __forceinline__ void mma_tf32(float* d, const uint* a, const uint* b) {
    asm volatile(
        "mma.sync.aligned.m16n8k8.row.col.f32.tf32.tf32.f32 "
        "{%0,%1,%2,%3}, {%4,%5,%6,%7}, {%8,%9}, {%0,%1,%2,%3};"
        : "+f"(d[0]), "+f"(d[1]), "+f"(d[2]), "+f"(d[3])
        : "r"(a[0]), "r"(a[1]), "r"(a[2]), "r"(a[3]), "r"(b[0]), "r"(b[1]));
}

__device__ __forceinline__ void cp16(uint smem_addr, const void* gptr) {
    asm volatile("cp.async.ca.shared.global [%0], [%1], 16;"
                 :: "r"(smem_addr), "l"(gptr));
}

// FMA-pipe exp (avoids MUFU serialization): exp(x) = 2^(x*log2e),
// round + deg-5 poly of 2^f on f in [-0.5,0.5] + exponent-bit ldexp.
__device__ __forceinline__ float fast_expf(float x) {
    x = fmaxf(x, -80.0f);                       // keep 2^n in normal range
    float y = x * 1.4426950408889634f;
    float z = y + 12582912.0f;                  // round-to-nearest via magic
    int   e = __float_as_int(z);                // low bits hold round(y)
    float n = z - 12582912.0f;
    float f = y - n;
    float p = 0.0013333558146428443f;
    p = fmaf(p, f, 0.009618129107628477f);
    p = fmaf(p, f, 0.05550410866482158f);
    p = fmaf(p, f, 0.2402265069591007f);
    p = fmaf(p, f, 0.6931471805599453f);
    p = fmaf(p, f, 1.0f);
    return __int_as_float(__float_as_int(p) + (e << 23));
}

// ---------------- kernel 1: 8x8 avg pool ----------------
__global__ void avgpool_kernel(const float* __restrict__ f) {
    int idx = blockIdx.x * blockDim.x + threadIdx.x;   // over BATCH*C*N
    int n  = idx & (N - 1);
    int bc = idx >> 10;
    int wp = n & (WP - 1);
    int hp = n >> 5;
    const float* src = f + ((size_t)bc * H + (size_t)hp * S) * W + (size_t)wp * S;
    float s = 0.f;
#pragma unroll
    for (int r = 0; r < S; r++) {
        float4 a = *(const float4*)(src + (size_t)r * W);
        float4 b = *(const float4*)(src + (size_t)r * W + 4);
        s += a.x + a.y + a.z + a.w + b.x + b.y + b.z + b.w;
    }
    g_xf[idx] = s * (1.f / 64.f);
}

// ---------------- kernel 2: q/k/v 1x1 convs (R5 version: coalesced staging) ----------------
// grid: (n_tiles=4, row_groups=20, batch=4), block 256
__global__ void qkv_kernel(const float* __restrict__ qw, const float* __restrict__ qb,
                           const float* __restrict__ kw, const float* __restrict__ kb,
                           const float* __restrict__ vw, const float* __restrict__ vb) {
    __shared__ float wsh[16][C];
    __shared__ float bsh[16];
    int b = blockIdx.z;
    int g = blockIdx.y;
    int n = blockIdx.x * 256 + threadIdx.x;

    const float* wsrc;
    const float* bsrc;
    float* dst;
    int r0;
    bool round_v;
    if (g < 2)      { wsrc = qw; bsrc = qb; dst = g_q + (size_t)b * KC * N; r0 = g * 16; round_v = false; }
    else if (g < 4) { wsrc = kw; bsrc = kb; dst = g_k + (size_t)b * KC * N; r0 = (g - 2) * 16; round_v = false; }
    else            { wsrc = vw; bsrc = vb; dst = g_v + (size_t)b * C * N;  r0 = (g - 4) * 16; round_v = true; }

    for (int i = threadIdx.x; i < 16 * C; i += 256)
        wsh[i >> 8][i & (C - 1)] = wsrc[(size_t)r0 * C + i];
    if (threadIdx.x < 16) bsh[threadIdx.x] = bsrc[r0 + threadIdx.x];
    __syncthreads();

    const float* xf = g_xf + (size_t)b * C * N + n;
    float acc[16];
#pragma unroll
    for (int r = 0; r < 16; r++) acc[r] = 0.f;

#pragma unroll 4
    for (int c = 0; c < C; c++) {
        float x = xf[(size_t)c * N];
#pragma unroll
        for (int r = 0; r < 16; r++) acc[r] = fmaf(wsh[r][c], x, acc[r]);
    }
#pragma unroll
    for (int r = 0; r < 16; r++) {
        float o = acc[r] + bsh[r];
        dst[(size_t)(r0 + r) * N + n] = round_v ? to_tf32(o) : o;
    }
}

// ---------------- kernel 3: energy + softmax (FMA-pipe exp, tf32-rounded store) ----------------
#define QT 8   // query rows per block
__global__ void attn_prob_kernel() {
    int b  = blockIdx.y;
    int n0 = blockIdx.x * QT;
    int tid  = threadIdx.x;
    int lane = tid & 31, wid = tid >> 5;

    __shared__ float qsh[QT][KC];
    __shared__ float red_m[QT][8];
    __shared__ float red_s[QT][8];

    {
        int r = tid >> 5, k = tid & 31;
        qsh[r][k] = g_q[((size_t)b * KC + k) * N + (n0 + r)];
    }
    __syncthreads();

    float e[QT][4];
#pragma unroll
    for (int r = 0; r < QT; r++)
#pragma unroll
        for (int j = 0; j < 4; j++) e[r][j] = 0.f;

    const float* Kp = g_k + (size_t)b * KC * N;
#pragma unroll 4
    for (int k = 0; k < KC; k++) {
        float kv0 = Kp[(size_t)k * N + tid];
        float kv1 = Kp[(size_t)k * N + tid + 256];
        float kv2 = Kp[(size_t)k * N + tid + 512];
        float kv3 = Kp[(size_t)k * N + tid + 768];
#pragma unroll
        for (int r = 0; r < QT; r++) {
            float qv = qsh[r][k];
            e[r][0] = fmaf(qv, kv0, e[r][0]);
            e[r][1] = fmaf(qv, kv1, e[r][1]);
            e[r][2] = fmaf(qv, kv2, e[r][2]);
            e[r][3] = fmaf(qv, kv3, e[r][3]);
        }
    }

    const float scale = 0.17677669529663687f;   // 32^-0.5
#pragma unroll
    for (int r = 0; r < QT; r++) {
#pragma unroll
        for (int j = 0; j < 4; j++) e[r][j] *= scale;
        float lm = fmaxf(fmaxf(e[r][0], e[r][1]), fmaxf(e[r][2], e[r][3]));
#pragma unroll
        for (int o = 16; o > 0; o >>= 1) lm = fmaxf(lm, __shfl_xor_sync(0xFFFFFFFFu, lm, o));
        if (lane == 0) red_m[r][wid] = lm;
    }
    __syncthreads();

#pragma unroll
    for (int r = 0; r < QT; r++) {
        float m2 = red_m[r][0];
#pragma unroll
        for (int w = 1; w < 8; w++) m2 = fmaxf(m2, red_m[r][w]);
        float ls = 0.f;
#pragma unroll
        for (int j = 0; j < 4; j++) { e[r][j] = fast_expf(e[r][j] - m2); ls += e[r][j]; }
#pragma unroll
        for (int o = 16; o > 0; o >>= 1) ls += __shfl_xor_sync(0xFFFFFFFFu, ls, o);
        if (lane == 0) red_s[r][wid] = ls;
    }
    __syncthreads();

    float* P = g_attn + (size_t)b * N * N;
#pragma unroll
    for (int r = 0; r < QT; r++) {
        float s2 = red_s[r][0];
#pragma unroll
        for (int w = 1; w < 8; w++) s2 += red_s[r][w];
        float inv = 1.f / s2;
#pragma unroll
        for (int j = 0; j < 4; j++)
            P[(size_t)(n0 + r) * N + tid + j * 256] = to_tf32(e[r][j] * inv);
    }
}

// ---------------- kernel 4: out = v @ attn^T via tf32 HMMA + cp.async pipeline ----------------
// block: 256 thr = 8 warps (2c x 4n), block tile 64(c) x 64(n), warp tile 32x16, k-chunk 32, 2-stage.
#define GBM 64
#define GBN 64
#define GBK 32
#define LDP 36   // smem row stride (words): bank = lane for fragment loads -> conflict-free
#define NCHUNK (N / GBK)
__global__ void out_gemm_kernel() {
    int b  = blockIdx.z;
    int c0 = blockIdx.y * GBM;
    int n0 = blockIdx.x * GBN;
    __shared__ __align__(16) uint Vs[2][GBM * LDP];
    __shared__ __align__(16) uint Ps[2][GBN * LDP];

    int tid  = threadIdx.x;      // 0..255
    int lane = tid & 31, wid = tid >> 5;
    int wm = (wid & 1) * 32;     // warp c offset
    int wn = (wid >> 1) * 16;    // warp n offset (0,16,32,48)

    const uint* V = (const uint*)g_v    + (size_t)b * C * N;
    const uint* P = (const uint*)g_attn + (size_t)b * N * N;

    int crow = tid >> 3;          // 0..31
    int cf4  = (tid & 7) * 4;

    float acc[2][2][4];
#pragma unroll
    for (int am = 0; am < 2; am++)
#pragma unroll
        for (int an = 0; an < 2; an++)
#pragma unroll
            for (int j = 0; j < 4; j++) acc[am][an][j] = 0.f;

    int r4  = lane >> 2;         // 0..7
    int q4  = lane & 3;          // 0..3

    // stage-0 prefetch
    {
#pragma unroll
        for (int i = 0; i < 2; i++) {
            int row = crow + i * 32;
            cp16((uint)__cvta_generic_to_shared(&Vs[0][row * LDP + cf4]),
                 V + (size_t)(c0 + row) * N + cf4);
            cp16((uint)__cvta_generic_to_shared(&Ps[0][row * LDP + cf4]),
                 P + (size_t)(n0 + row) * N + cf4);
        }
        asm volatile("cp.async.commit_group;");
    }

    for (int ch = 0; ch < NCHUNK; ch++) {
        int s = ch & 1;
        if (ch + 1 < NCHUNK) {
            int m1 = (ch + 1) * GBK;
#pragma unroll
            for (int i = 0; i < 2; i++) {
                int row = crow + i * 32;
                cp16((uint)__cvta_generic_to_shared(&Vs[s ^ 1][row * LDP + cf4]),
                     V + (size_t)(c0 + row) * N + m1 + cf4);
                cp16((uint)__cvta_generic_to_shared(&Ps[s ^ 1][row * LDP + cf4]),
                     P + (size_t)(n0 + row) * N + m1 + cf4);
            }
            asm volatile("cp.async.commit_group;");
            asm volatile("cp.async.wait_group 1;");
        } else {
            asm volatile("cp.async.wait_group 0;");
        }
        __syncthreads();

        const uint* Vss = Vs[s];
        const uint* Pss = Ps[s];
#pragma unroll
        for (int k8 = 0; k8 < GBK; k8 += 8) {
            uint a[2][4], bb[2][2];
#pragma unroll
            for (int am = 0; am < 2; am++) {
                int base = (wm + am * 16 + r4) * LDP + k8 + q4;
                a[am][0] = Vss[base];
                a[am][1] = Vss[base + 8 * LDP];
                a[am][2] = Vss[base + 4];
                a[am][3] = Vss[base + 8 * LDP + 4];
            }
#pragma unroll
            for (int an = 0; an < 2; an++) {
                int base = (wn + an * 8 + r4) * LDP + k8 + q4;
                bb[an][0] = Pss[base];
                bb[an][1] = Pss[base + 4];
            }
#pragma unroll
            for (int am = 0; am < 2; am++)
#pragma unroll
                for (int an = 0; an < 2; an++)
                    mma_tf32(acc[am][an], a[am], bb[an]);
        }
        __syncthreads();
    }

    float* O = g_out + (size_t)b * C * N;
    int cc = (lane & 3) * 2;
#pragma unroll
    for (int am = 0; am < 2; am++)
#pragma unroll
        for (int an = 0; an < 2; an++) {
            int cr = c0 + wm + am * 16 + r4;
            int ncol = n0 + wn + an * 8 + cc;
            float2 lo; lo.x = acc[am][an][0]; lo.y = acc[am][an][1];
            float2 hi; hi.x = acc[am][an][2]; hi.y = acc[am][an][3];
            *(float2*)(O + (size_t)cr * N + ncol)       = lo;
            *(float2*)(O + (size_t)(cr + 8) * N + ncol) = hi;
        }
}

// ---------------- kernel 5: nearest 8x upsample + residual ----------------
__global__ void upsample_add_kernel(const float* __restrict__ f, float* __restrict__ out) {
    size_t idx = (size_t)blockIdx.x * blockDim.x + threadIdx.x;  // over B*C*H*W/4
    int w4 = (int)(idx & 63);            // W/4 = 64
    int h  = (int)((idx >> 6) & 255);
    size_t bc = idx >> 14;
    int hp = h >> 3;
    int wp = w4 >> 1;                    // (w4*4)/8
    float s = g_out[bc * N + (size_t)hp * WP + wp];
    float4 a = ((const float4*)f)[idx];
    a.x += s; a.y += s; a.z += s; a.w += s;
    ((float4*)out)[idx] = a;
}

// ---------------- launch ----------------
extern "C" void kernel_launch(void* const* d_in, const int* in_sizes, int n_in,
                              void* d_out, int out_size) {
    const float* f  = (const float*)d_in[0];
    const float* qw = (const float*)d_in[1];
    const float* qb = (const float*)d_in[2];
    const float* kw = (const float*)d_in[3];
    const float* kb = (const float*)d_in[4];
    const float* vw = (const float*)d_in[5];
    const float* vb = (const float*)d_in[6];
    float* out = (float*)d_out;

    avgpool_kernel<<<(BATCH * C * N) / 256, 256>>>(f);
    qkv_kernel<<<dim3(4, 20, BATCH), 256>>>(qw, qb, kw, kb, vw, vb);
    attn_prob_kernel<<<dim3(N / QT, BATCH), 256>>>();
    out_gemm_kernel<<<dim3(N / GBN, C / GBM, BATCH), 256>>>();
    upsample_add_kernel<<<(BATCH * C * H * (W / 4)) / 256, 256>>>(f, out);
}

// round 8
// speedup vs baseline: 1.1389x; 1.0205x over previous
#include <cuda_runtime.h>

#define BATCH 4
#define C 256
#define H 256
#define W 256
#define S 8
#define HP 32
#define WP 32
#define N 1024     // HP*WP tokens
#define KC 32      // key channels

typedef unsigned int uint;

// ---------------- device scratch (no allocs allowed) ----------------
__device__ float g_xf[BATCH * C * N];        // pooled features  [b][c][n]   4 MB
__device__ float g_q[BATCH * KC * N];        // q                [b][k][n]
__device__ float g_k[BATCH * KC * N];        // k                [b][k][n]
__device__ float g_v[BATCH * C * N];         // v (tf32-rounded) [b][c][n]   4 MB
__device__ float g_attn[BATCH * N * N];      // probs (tf32-rnd) [b][n][m]  16 MB
__device__ float g_out[BATCH * C * N];       // attn output      [b][c][n]   4 MB

__device__ __forceinline__ float to_tf32(float x) {
    float r; asm("cvt.rna.tf32.f32 %0, %1;" : "=f"(r) : "f"(x)); return r;
}

__device__ __forceinline__ void mma_tf32(float* d, const uint* a, const uint* b) {
    asm volatile(
        "mma.sync.aligned.m16n8k8.row.col.f32.tf32.tf32.f32 "
        "{%0,%1,%2,%3}, {%4,%5,%6,%7}, {%8,%9}, {%0,%1,%2,%3};"
        : "+f"(d[0]), "+f"(d[1]), "+f"(d[2]), "+f"(d[3])
        : "r"(a[0]), "r"(a[1]), "r"(a[2]), "r"(a[3]), "r"(b[0]), "r"(b[1]));
}

__device__ __forceinline__ void cp16(uint smem_addr, const void* gptr) {
    asm volatile("cp.async.ca.shared.global [%0], [%1], 16;"
                 :: "r"(smem_addr), "l"(gptr));
}

// FMA-pipe exp (avoids MUFU serialization): exp(x) = 2^(x*log2e),
// round + deg-5 poly of 2^f on f in [-0.5,0.5] + exponent-bit ldexp.
__device__ __forceinline__ float fast_expf(float x) {
    x = fmaxf(x, -80.0f);                       // keep 2^n in normal range
    float y = x * 1.4426950408889634f;
    float z = y + 12582912.0f;                  // round-to-nearest via magic
    int   e = __float_as_int(z);                // low bits hold round(y)
    float n = z - 12582912.0f;
    float f = y - n;
    float p = 0.0013333558146428443f;
    p = fmaf(p, f, 0.009618129107628477f);
    p = fmaf(p, f, 0.05550410866482158f);
    p = fmaf(p, f, 0.2402265069591007f);
    p = fmaf(p, f, 0.6931471805599453f);
    p = fmaf(p, f, 1.0f);
    return __int_as_float(__float_as_int(p) + (e << 23));
}

// ---------------- kernel 1: 8x8 avg pool ----------------
__global__ void avgpool_kernel(const float* __restrict__ f) {
    int idx = blockIdx.x * blockDim.x + threadIdx.x;   // over BATCH*C*N
    int n  = idx & (N - 1);
    int bc = idx >> 10;
    int wp = n & (WP - 1);
    int hp = n >> 5;
    const float* src = f + ((size_t)bc * H + (size_t)hp * S) * W + (size_t)wp * S;
    float s = 0.f;
#pragma unroll
    for (int r = 0; r < S; r++) {
        float4 a = *(const float4*)(src + (size_t)r * W);
        float4 b = *(const float4*)(src + (size_t)r * W + 4);
        s += a.x + a.y + a.z + a.w + b.x + b.y + b.z + b.w;
    }
    g_xf[idx] = s * (1.f / 64.f);
}

// ---------------- kernel 2: q/k/v 1x1 convs (R5 version: coalesced staging) ----------------
// grid: (n_tiles=4, row_groups=20, batch=4), block 256
__global__ void qkv_kernel(const float* __restrict__ qw, const float* __restrict__ qb,
                           const float* __restrict__ kw, const float* __restrict__ kb,
                           const float* __restrict__ vw, const float* __restrict__ vb) {
    __shared__ float wsh[16][C];
    __shared__ float bsh[16];
    int b = blockIdx.z;
    int g = blockIdx.y;
    int n = blockIdx.x * 256 + threadIdx.x;

    const float* wsrc;
    const float* bsrc;
    float* dst;
    int r0;
    bool round_v;
    if (g < 2)      { wsrc = qw; bsrc = qb; dst = g_q + (size_t)b * KC * N; r0 = g * 16; round_v = false; }
    else if (g < 4) { wsrc = kw; bsrc = kb; dst = g_k + (size_t)b * KC * N; r0 = (g - 2) * 16; round_v = false; }
    else            { wsrc = vw; bsrc = vb; dst = g_v + (size_t)b * C * N;  r0 = (g - 4) * 16; round_v = true; }

    for (int i = threadIdx.x; i < 16 * C; i += 256)
        wsh[i >> 8][i & (C - 1)] = wsrc[(size_t)r0 * C + i];
    if (threadIdx.x < 16) bsh[threadIdx.x] = bsrc[r0 + threadIdx.x];
    __syncthreads();

    const float* xf = g_xf + (size_t)b * C * N + n;
    float acc[16];
#pragma unroll
    for (int r = 0; r < 16; r++) acc[r] = 0.f;

#pragma unroll 4
    for (int c = 0; c < C; c++) {
        float x = xf[(size_t)c * N];
#pragma unroll
        for (int r = 0; r < 16; r++) acc[r] = fmaf(wsh[r][c], x, acc[r]);
    }
#pragma unroll
    for (int r = 0; r < 16; r++) {
        float o = acc[r] + bsh[r];
        dst[(size_t)(r0 + r) * N + n] = round_v ? to_tf32(o) : o;
    }
}

// ---------------- kernel 3: energy + softmax (FMA-pipe exp, tf32-rounded store) ----------------
#define QT 8   // query rows per block
__global__ void attn_prob_kernel() {
    int b  = blockIdx.y;
    int n0 = blockIdx.x * QT;
    int tid  = threadIdx.x;
    int lane = tid & 31, wid = tid >> 5;

    __shared__ float qsh[QT][KC];
    __shared__ float red_m[QT][8];
    __shared__ float red_s[QT][8];

    {
        int r = tid >> 5, k = tid & 31;
        qsh[r][k] = g_q[((size_t)b * KC + k) * N + (n0 + r)];
    }
    __syncthreads();

    float e[QT][4];
#pragma unroll
    for (int r = 0; r < QT; r++)
#pragma unroll
        for (int j = 0; j < 4; j++) e[r][j] = 0.f;

    const float* Kp = g_k + (size_t)b * KC * N;
#pragma unroll 4
    for (int k = 0; k < KC; k++) {
        float kv0 = Kp[(size_t)k * N + tid];
        float kv1 = Kp[(size_t)k * N + tid + 256];
        float kv2 = Kp[(size_t)k * N + tid + 512];
        float kv3 = Kp[(size_t)k * N + tid + 768];
#pragma unroll
        for (int r = 0; r < QT; r++) {
            float qv = qsh[r][k];
            e[r][0] = fmaf(qv, kv0, e[r][0]);
            e[r][1] = fmaf(qv, kv1, e[r][1]);
            e[r][2] = fmaf(qv, kv2, e[r][2]);
            e[r][3] = fmaf(qv, kv3, e[r][3]);
        }
    }

    const float scale = 0.17677669529663687f;   // 32^-0.5
#pragma unroll
    for (int r = 0; r < QT; r++) {
#pragma unroll
        for (int j = 0; j < 4; j++) e[r][j] *= scale;
        float lm = fmaxf(fmaxf(e[r][0], e[r][1]), fmaxf(e[r][2], e[r][3]));
#pragma unroll
        for (int o = 16; o > 0; o >>= 1) lm = fmaxf(lm, __shfl_xor_sync(0xFFFFFFFFu, lm, o));
        if (lane == 0) red_m[r][wid] = lm;
    }
    __syncthreads();

#pragma unroll
    for (int r = 0; r < QT; r++) {
        float m2 = red_m[r][0];
#pragma unroll
        for (int w = 1; w < 8; w++) m2 = fmaxf(m2, red_m[r][w]);
        float ls = 0.f;
#pragma unroll
        for (int j = 0; j < 4; j++) { e[r][j] = fast_expf(e[r][j] - m2); ls += e[r][j]; }
#pragma unroll
        for (int o = 16; o > 0; o >>= 1) ls += __shfl_xor_sync(0xFFFFFFFFu, ls, o);
        if (lane == 0) red_s[r][wid] = ls;
    }
    __syncthreads();

    float* P = g_attn + (size_t)b * N * N;
#pragma unroll
    for (int r = 0; r < QT; r++) {
        float s2 = red_s[r][0];
#pragma unroll
        for (int w = 1; w < 8; w++) s2 += red_s[r][w];
        float inv = 1.f / s2;
#pragma unroll
        for (int j = 0; j < 4; j++)
            P[(size_t)(n0 + r) * N + tid + j * 256] = to_tf32(e[r][j] * inv);
    }
}

// ---------------- kernel 4: out = v @ attn^T via tf32 HMMA + cp.async pipeline ----------------
// block: 256 thr = 8 warps (2c x 4n), block tile 64(c) x 64(n), warp tile 32x16, k-chunk 32, 2-stage.
#define GBM 64
#define GBN 64
#define GBK 32
#define LDP 36   // smem row stride (words): bank = lane for fragment loads -> conflict-free
#define NCHUNK (N / GBK)
__global__ void out_gemm_kernel() {
    int b  = blockIdx.z;
    int c0 = blockIdx.y * GBM;
    int n0 = blockIdx.x * GBN;
    __shared__ __align__(16) uint Vs[2][GBM * LDP];
    __shared__ __align__(16) uint Ps[2][GBN * LDP];

    int tid  = threadIdx.x;      // 0..255
    int lane = tid & 31, wid = tid >> 5;
    int wm = (wid & 1) * 32;     // warp c offset
    int wn = (wid >> 1) * 16;    // warp n offset (0,16,32,48)

    const uint* V = (const uint*)g_v    + (size_t)b * C * N;
    const uint* P = (const uint*)g_attn + (size_t)b * N * N;

    int crow = tid >> 3;          // 0..31
    int cf4  = (tid & 7) * 4;

    float acc[2][2][4];
#pragma unroll
    for (int am = 0; am < 2; am++)
#pragma unroll
        for (int an = 0; an < 2; an++)
#pragma unroll
            for (int j = 0; j < 4; j++) acc[am][an][j] = 0.f;

    int r4  = lane >> 2;         // 0..7
    int q4  = lane & 3;          // 0..3

    // stage-0 prefetch
    {
#pragma unroll
        for (int i = 0; i < 2; i++) {
            int row = crow + i * 32;
            cp16((uint)__cvta_generic_to_shared(&Vs[0][row * LDP + cf4]),
                 V + (size_t)(c0 + row) * N + cf4);
            cp16((uint)__cvta_generic_to_shared(&Ps[0][row * LDP + cf4]),
                 P + (size_t)(n0 + row) * N + cf4);
        }
        asm volatile("cp.async.commit_group;");
    }

    for (int ch = 0; ch < NCHUNK; ch++) {
        int s = ch & 1;
        if (ch + 1 < NCHUNK) {
            int m1 = (ch + 1) * GBK;
#pragma unroll
            for (int i = 0; i < 2; i++) {
                int row = crow + i * 32;
                cp16((uint)__cvta_generic_to_shared(&Vs[s ^ 1][row * LDP + cf4]),
                     V + (size_t)(c0 + row) * N + m1 + cf4);
                cp16((uint)__cvta_generic_to_shared(&Ps[s ^ 1][row * LDP + cf4]),
                     P + (size_t)(n0 + row) * N + m1 + cf4);
            }
            asm volatile("cp.async.commit_group;");
            asm volatile("cp.async.wait_group 1;");
        } else {
            asm volatile("cp.async.wait_group 0;");
        }
        __syncthreads();

        const uint* Vss = Vs[s];
        const uint* Pss = Ps[s];
#pragma unroll
        for (int k8 = 0; k8 < GBK; k8 += 8) {
            uint a[2][4], bb[2][2];
#pragma unroll
            for (int am = 0; am < 2; am++) {
                int base = (wm + am * 16 + r4) * LDP + k8 + q4;
                a[am][0] = Vss[base];
                a[am][1] = Vss[base + 8 * LDP];
                a[am][2] = Vss[base + 4];
                a[am][3] = Vss[base + 8 * LDP + 4];
            }
#pragma unroll
            for (int an = 0; an < 2; an++) {
                int base = (wn + an * 8 + r4) * LDP + k8 + q4;
                bb[an][0] = Pss[base];
                bb[an][1] = Pss[base + 4];
            }
#pragma unroll
            for (int am = 0; am < 2; am++)
#pragma unroll
                for (int an = 0; an < 2; an++)
                    mma_tf32(acc[am][an], a[am], bb[an]);
        }
        __syncthreads();
    }

    float* O = g_out + (size_t)b * C * N;
    int cc = (lane & 3) * 2;
#pragma unroll
    for (int am = 0; am < 2; am++)
#pragma unroll
        for (int an = 0; an < 2; an++) {
            int cr = c0 + wm + am * 16 + r4;
            int ncol = n0 + wn + an * 8 + cc;
            float2 lo; lo.x = acc[am][an][0]; lo.y = acc[am][an][1];
            float2 hi; hi.x = acc[am][an][2]; hi.y = acc[am][an][3];
            *(float2*)(O + (size_t)cr * N + ncol)       = lo;
            *(float2*)(O + (size_t)(cr + 8) * N + ncol) = hi;
        }
}

// ---------------- kernel 5: nearest 8x upsample + residual ----------------
__global__ void upsample_add_kernel(const float* __restrict__ f, float* __restrict__ out) {
    size_t idx = (size_t)blockIdx.x * blockDim.x + threadIdx.x;  // over B*C*H*W/4
    int w4 = (int)(idx & 63);            // W/4 = 64
    int h  = (int)((idx >> 6) & 255);
    size_t bc = idx >> 14;
    int hp = h >> 3;
    int wp = w4 >> 1;                    // (w4*4)/8
    float s = g_out[bc * N + (size_t)hp * WP + wp];
    float4 a = ((const float4*)f)[idx];
    a.x += s; a.y += s; a.z += s; a.w += s;
    ((float4*)out)[idx] = a;
}

// ---------------- launch ----------------
extern "C" void kernel_launch(void* const* d_in, const int* in_sizes, int n_in,
                              void* d_out, int out_size) {
    const float* f  = (const float*)d_in[0];
    const float* qw = (const float*)d_in[1];
    const float* qb = (const float*)d_in[2];
    const float* kw = (const float*)d_in[3];
    const float* kb = (const float*)d_in[4];
    const float* vw = (const float*)d_in[5];
    const float* vb = (const float*)d_in[6];
    float* out = (float*)d_out;

    avgpool_kernel<<<(BATCH * C * N) / 256, 256>>>(f);
    qkv_kernel<<<dim3(4, 20, BATCH), 256>>>(qw, qb, kw, kb, vw, vb);
    attn_prob_kernel<<<dim3(N / QT, BATCH), 256>>>();
    out_gemm_kernel<<<dim3(N / GBN, C / GBM, BATCH), 256>>>();
    upsample_add_kernel<<<(BATCH * C * H * (W / 4)) / 256, 256>>>(f, out);
}

// round 9
// speedup vs baseline: 1.4078x; 1.2361x over previous
#include <cuda_runtime.h>

#define BATCH 4
#define C 256
#define H 256
#define W 256
#define S 8
#define HP 32
#define WP 32
#define N 1024     // HP*WP tokens
#define KC 32      // key channels

typedef unsigned int uint;

// ---------------- device scratch (no allocs allowed) ----------------
__device__ float g_xf[BATCH * C * N];        // pooled features  [b][c][n]   4 MB
__device__ float g_qT[BATCH * N * KC];       // q transposed     [b][n][k]
__device__ float g_kT[BATCH * N * KC];       // k transposed     [b][m][k]
__device__ float g_v[BATCH * C * N];         // v (tf32-rounded) [b][c][n]   4 MB
__device__ float g_attn[BATCH * N * N];      // exp(energy), unnormalized [b][n][m]
__device__ float g_rsum[BATCH * N];          // softmax row sums
__device__ float g_out[BATCH * C * N];       // attn output      [b][c][n]

__device__ __forceinline__ float to_tf32(float x) {
    float r; asm("cvt.rna.tf32.f32 %0, %1;" : "=f"(r) : "f"(x)); return r;
}

__device__ __forceinline__ void mma_tf32(float* d, const uint* a, const uint* b) {
    asm volatile(
        "mma.sync.aligned.m16n8k8.row.col.f32.tf32.tf32.f32 "
        "{%0,%1,%2,%3}, {%4,%5,%6,%7}, {%8,%9}, {%0,%1,%2,%3};"
        : "+f"(d[0]), "+f"(d[1]), "+f"(d[2]), "+f"(d[3])
        : "r"(a[0]), "r"(a[1]), "r"(a[2]), "r"(a[3]), "r"(b[0]), "r"(b[1]));
}

__device__ __forceinline__ void cp16(uint smem_addr, const void* gptr) {
    asm volatile("cp.async.ca.shared.global [%0], [%1], 16;"
                 :: "r"(smem_addr), "l"(gptr));
}

// FMA-pipe exp: exp(x) = 2^(x*log2e), magic-number round + deg-5 poly + exp-bit ldexp.
__device__ __forceinline__ float fast_expf(float x) {
    x = fmaxf(x, -80.0f);
    float y = x * 1.4426950408889634f;
    float z = y + 12582912.0f;
    int   e = __float_as_int(z);
    float n = z - 12582912.0f;
    float f = y - n;
    float p = 0.0013333558146428443f;
    p = fmaf(p, f, 0.009618129107628477f);
    p = fmaf(p, f, 0.05550410866482158f);
    p = fmaf(p, f, 0.2402265069591007f);
    p = fmaf(p, f, 0.6931471805599453f);
    p = fmaf(p, f, 1.0f);
    return __int_as_float(__float_as_int(p) + (e << 23));
}

// ---------------- kernel 1: 8x8 avg pool ----------------
__global__ void avgpool_kernel(const float* __restrict__ f) {
    int idx = blockIdx.x * blockDim.x + threadIdx.x;   // over BATCH*C*N
    int n  = idx & (N - 1);
    int bc = idx >> 10;
    int wp = n & (WP - 1);
    int hp = n >> 5;
    const float* src = f + ((size_t)bc * H + (size_t)hp * S) * W + (size_t)wp * S;
    float s = 0.f;
#pragma unroll
    for (int r = 0; r < S; r++) {
        float4 a = *(const float4*)(src + (size_t)r * W);
        float4 b = *(const float4*)(src + (size_t)r * W + 4);
        s += a.x + a.y + a.z + a.w + b.x + b.y + b.z + b.w;
    }
    g_xf[idx] = s * (1.f / 64.f);
}

// ---------------- kernel 2: q/k/v via tf32 HMMA ----------------
// D[r][n] = sum_c Wcat[r][c] * xf[c][n].  grid (ntile=16, rgroup=5, batch=4), block 256.
// rgroup 0: rows 0..31 = qw, 32..63 = kw (outputs stored TRANSPOSED [n][k]).
// rgroup 1..4: vw rows (g-1)*64.. (output [c][n], tf32-rounded).
#define QLDA 36
#define QLDB 72
__global__ void qkv_mma_kernel(const float* __restrict__ qw, const float* __restrict__ qb,
                               const float* __restrict__ kw, const float* __restrict__ kb,
                               const float* __restrict__ vw, const float* __restrict__ vb) {
    int b  = blockIdx.z;
    int g  = blockIdx.y;
    int n0 = blockIdx.x * 64;

    __shared__ __align__(16) float As[2][64 * QLDA];   // A[m=64][k=32]
    __shared__ __align__(16) float Bs[2][32 * QLDB];   // B[k=32][n=64]
    __shared__ float bsh[64];

    int tid  = threadIdx.x;
    int lane = tid & 31, wid = tid >> 5;
    int wm = (wid & 1) * 32;
    int wn = (wid >> 1) * 16;
    int r4 = lane >> 2, q4 = lane & 3;

    // per-thread A slots: (rowA0, segA) and (rowA0+32, segA)
    int rowA0 = tid >> 3;          // 0..31
    int segA  = tid & 7;           // 0..7 (16B units of 32-float row)
    // per-thread B slots: rows rowB0, rowB0+16, seg 0..15
    int rowB0 = tid >> 4;          // 0..15
    int segB  = tid & 15;

    // source row pointers for A (row in 0..63 of concatenated W)
    const float* arow0;
    const float* arow1;
    int row1 = rowA0 + 32;
    if (g == 0) {
        arow0 = qw + (size_t)rowA0 * C;
        arow1 = kw + (size_t)(row1 - 32) * C;
    } else {
        arow0 = vw + (size_t)((g - 1) * 64 + rowA0) * C;
        arow1 = vw + (size_t)((g - 1) * 64 + row1) * C;
    }
    // bias staging
    if (tid < 64) {
        float bv;
        if (g == 0) bv = (tid < 32) ? qb[tid] : kb[tid - 32];
        else        bv = vb[(g - 1) * 64 + tid];
        bsh[tid] = bv;
    }

    const float* xfb = g_xf + (size_t)b * C * N;

    float acc[2][2][4];
#pragma unroll
    for (int am = 0; am < 2; am++)
#pragma unroll
        for (int an = 0; an < 2; an++)
#pragma unroll
            for (int j = 0; j < 4; j++) acc[am][an][j] = 0.f;

    // prefetch chunk 0
    {
        cp16((uint)__cvta_generic_to_shared(&As[0][rowA0 * QLDA + segA * 4]), arow0 + segA * 4);
        cp16((uint)__cvta_generic_to_shared(&As[0][row1  * QLDA + segA * 4]), arow1 + segA * 4);
        cp16((uint)__cvta_generic_to_shared(&Bs[0][rowB0 * QLDB + segB * 4]),
             xfb + (size_t)rowB0 * N + n0 + segB * 4);
        cp16((uint)__cvta_generic_to_shared(&Bs[0][(rowB0 + 16) * QLDB + segB * 4]),
             xfb + (size_t)(rowB0 + 16) * N + n0 + segB * 4);
        asm volatile("cp.async.commit_group;");
    }

    for (int ch = 0; ch < 8; ch++) {          // C/32 = 8 chunks
        int s = ch & 1;
        if (ch + 1 < 8) {
            int c1 = (ch + 1) * 32;
            cp16((uint)__cvta_generic_to_shared(&As[s ^ 1][rowA0 * QLDA + segA * 4]), arow0 + c1 + segA * 4);
            cp16((uint)__cvta_generic_to_shared(&As[s ^ 1][row1  * QLDA + segA * 4]), arow1 + c1 + segA * 4);
            cp16((uint)__cvta_generic_to_shared(&Bs[s ^ 1][rowB0 * QLDB + segB * 4]),
                 xfb + (size_t)(c1 + rowB0) * N + n0 + segB * 4);
            cp16((uint)__cvta_generic_to_shared(&Bs[s ^ 1][(rowB0 + 16) * QLDB + segB * 4]),
                 xfb + (size_t)(c1 + rowB0 + 16) * N + n0 + segB * 4);
            asm volatile("cp.async.commit_group;");
            asm volatile("cp.async.wait_group 1;");
        } else {
            asm volatile("cp.async.wait_group 0;");
        }
        __syncthreads();

        const uint* Ass = (const uint*)As[s];
        const uint* Bss = (const uint*)Bs[s];
#pragma unroll
        for (int k8 = 0; k8 < 32; k8 += 8) {
            uint a[2][4], bb[2][2];
#pragma unroll
            for (int am = 0; am < 2; am++) {
                int base = (wm + am * 16 + r4) * QLDA + k8 + q4;
                a[am][0] = Ass[base];
                a[am][1] = Ass[base + 8 * QLDA];
                a[am][2] = Ass[base + 4];
                a[am][3] = Ass[base + 8 * QLDA + 4];
            }
#pragma unroll
            for (int an = 0; an < 2; an++) {
                int nb = wn + an * 8 + r4;
                bb[an][0] = Bss[(k8 + q4) * QLDB + nb];
                bb[an][1] = Bss[(k8 + q4 + 4) * QLDB + nb];
            }
#pragma unroll
            for (int am = 0; am < 2; am++)
#pragma unroll
                for (int an = 0; an < 2; an++)
                    mma_tf32(acc[am][an], a[am], bb[an]);
        }
        __syncthreads();
    }

    int cc = (lane & 3) * 2;
    if (g == 0) {
        // transposed scattered stores: qT/kT [n][kc]
        float* QT = g_qT + (size_t)b * N * KC;
        float* KT = g_kT + (size_t)b * N * KC;
#pragma unroll
        for (int am = 0; am < 2; am++)
#pragma unroll
            for (int an = 0; an < 2; an++) {
                int r  = wm + am * 16 + r4;
                int nc = n0 + wn + an * 8 + cc;
#pragma unroll
                for (int dr = 0; dr < 2; dr++) {      // rows r, r+8
                    int rr = r + dr * 8;
                    float d0 = acc[am][an][dr * 2 + 0] + bsh[rr];
                    float d1 = acc[am][an][dr * 2 + 1] + bsh[rr];
                    float* dst = (rr < 32) ? (QT + rr) : (KT + rr - 32);
                    dst[(size_t)nc * KC]       = to_tf32(d0);
                    dst[(size_t)(nc + 1) * KC] = to_tf32(d1);
                }
            }
    } else {
        float* V = g_v + (size_t)b * C * N + (size_t)(g - 1) * 64 * N;
#pragma unroll
        for (int am = 0; am < 2; am++)
#pragma unroll
            for (int an = 0; an < 2; an++) {
                int r  = wm + am * 16 + r4;
                int nc = n0 + wn + an * 8 + cc;
                float2 lo; lo.x = to_tf32(acc[am][an][0] + bsh[r]);     lo.y = to_tf32(acc[am][an][1] + bsh[r]);
                float2 hi; hi.x = to_tf32(acc[am][an][2] + bsh[r + 8]); hi.y = to_tf32(acc[am][an][3] + bsh[r + 8]);
                *(float2*)(V + (size_t)r * N + nc)       = lo;
                *(float2*)(V + (size_t)(r + 8) * N + nc) = hi;
            }
    }
}

// ---------------- kernel 3: energy via HMMA + exp (unnormalized) + row sums ----------------
// E[n][m] = exp(scale * sum_k qT[n][k]*kT[m][k]); s_n accumulated to g_rsum.
// grid (64 ntiles of 16, batch), block 256 = 8 warps, warp covers 16 m per chunk of 128.
#define ALD 36
__global__ void attn_mma_kernel() {
    int b  = blockIdx.y;
    int n0 = blockIdx.x * 16;
    int tid  = threadIdx.x;
    int lane = tid & 31, w = tid >> 5;
    int r4 = lane >> 2, q4 = lane & 3;

    __shared__ __align__(16) float Asm[16 * ALD];        // qT tile [16 n][32 k]
    __shared__ __align__(16) float Bs[2][128 * ALD];     // kT chunk [128 m][32 k]
    __shared__ float red[16][8];

    const float* QT = g_qT + (size_t)b * N * KC;
    const float* KT = g_kT + (size_t)b * N * KC;
    float* P = g_attn + (size_t)b * N * N;

    // stage A (16 rows x 8 segs = 128 cp16) + B chunk 0
    if (tid < 128) {
        int row = tid >> 3, seg = tid & 7;
        cp16((uint)__cvta_generic_to_shared(&Asm[row * ALD + seg * 4]),
             QT + (size_t)(n0 + row) * KC + seg * 4);
    }
    {
        int row = tid >> 1, seg = tid & 1;   // 128 rows x 8 segs: 4 slots/thread
#pragma unroll
        for (int i = 0; i < 4; i++) {
            int slot = tid + i * 256;
            int rr = slot >> 3, ss = slot & 7;
            cp16((uint)__cvta_generic_to_shared(&Bs[0][rr * ALD + ss * 4]),
                 KT + (size_t)rr * KC + ss * 4);
        }
        (void)row; (void)seg;
        asm volatile("cp.async.commit_group;");
    }

    uint a_all[4][4];
    float rs0 = 0.f, rs1 = 0.f;
    const float scale = 0.17677669529663687f;   // 32^-0.5

    for (int ch = 0; ch < 8; ch++) {
        int s = ch & 1;
        if (ch + 1 < 8) {
            int m1 = (ch + 1) * 128;
#pragma unroll
            for (int i = 0; i < 4; i++) {
                int slot = tid + i * 256;
                int rr = slot >> 3, ss = slot & 7;
                cp16((uint)__cvta_generic_to_shared(&Bs[s ^ 1][rr * ALD + ss * 4]),
                     KT + (size_t)(m1 + rr) * KC + ss * 4);
            }
            asm volatile("cp.async.commit_group;");
            asm volatile("cp.async.wait_group 1;");
        } else {
            asm volatile("cp.async.wait_group 0;");
        }
        __syncthreads();

        if (ch == 0) {
            const uint* Au = (const uint*)Asm;
#pragma unroll
            for (int k8 = 0; k8 < 4; k8++) {
                int base = r4 * ALD + k8 * 8 + q4;
                a_all[k8][0] = Au[base];
                a_all[k8][1] = Au[base + 8 * ALD];
                a_all[k8][2] = Au[base + 4];
                a_all[k8][3] = Au[base + 8 * ALD + 4];
            }
        }

        const uint* Bu = (const uint*)Bs[s];
        float acc[2][4];
#pragma unroll
        for (int at = 0; at < 2; at++)
#pragma unroll
            for (int j = 0; j < 4; j++) acc[at][j] = 0.f;

#pragma unroll
        for (int k8 = 0; k8 < 4; k8++) {
            uint bb[2][2];
#pragma unroll
            for (int at = 0; at < 2; at++) {
                int mb = (w * 16 + at * 8 + r4) * ALD + k8 * 8 + q4;
                bb[at][0] = Bu[mb];
                bb[at][1] = Bu[mb + 4];
            }
#pragma unroll
            for (int at = 0; at < 2; at++)
                mma_tf32(acc[at], a_all[k8], bb[at]);
        }

        // exp + store + row-sum accumulation
        int cc = q4 * 2;
        int mbase = ch * 128 + w * 16;
#pragma unroll
        for (int at = 0; at < 2; at++) {
            float e0 = fast_expf(acc[at][0] * scale);
            float e1 = fast_expf(acc[at][1] * scale);
            float e2 = fast_expf(acc[at][2] * scale);
            float e3 = fast_expf(acc[at][3] * scale);
            rs0 += e0 + e1;
            rs1 += e2 + e3;
            int mc = mbase + at * 8 + cc;
            float2 lo; lo.x = to_tf32(e0); lo.y = to_tf32(e1);
            float2 hi; hi.x = to_tf32(e2); hi.y = to_tf32(e3);
            *(float2*)(P + (size_t)(n0 + r4) * N + mc)     = lo;
            *(float2*)(P + (size_t)(n0 + r4 + 8) * N + mc) = hi;
        }
        __syncthreads();
    }

    // reduce row sums: over q4 lanes within row group
    rs0 += __shfl_xor_sync(0xFFFFFFFFu, rs0, 1);
    rs0 += __shfl_xor_sync(0xFFFFFFFFu, rs0, 2);
    rs1 += __shfl_xor_sync(0xFFFFFFFFu, rs1, 1);
    rs1 += __shfl_xor_sync(0xFFFFFFFFu, rs1, 2);
    if (q4 == 0) { red[r4][w] = rs0; red[r4 + 8][w] = rs1; }
    __syncthreads();
    if (tid < 16) {
        float s = 0.f;
#pragma unroll
        for (int j = 0; j < 8; j++) s += red[tid][j];
        g_rsum[(size_t)b * N + n0 + tid] = s;
    }
}

// ---------------- kernel 4: out = v @ E^T (scaled by 1/rsum) via tf32 HMMA ----------------
#define GBM 64
#define GBN 64
#define GBK 32
#define LDP 36
#define NCHUNK (N / GBK)
__global__ void out_gemm_kernel() {
    int b  = blockIdx.z;
    int c0 = blockIdx.y * GBM;
    int n0 = blockIdx.x * GBN;
    __shared__ __align__(16) uint Vs[2][GBM * LDP];
    __shared__ __align__(16) uint Ps[2][GBN * LDP];

    int tid  = threadIdx.x;      // 0..255
    int lane = tid & 31, wid = tid >> 5;
    int wm = (wid & 1) * 32;
    int wn = (wid >> 1) * 16;

    const uint* V = (const uint*)g_v    + (size_t)b * C * N;
    const uint* P = (const uint*)g_attn + (size_t)b * N * N;

    int crow = tid >> 3;
    int cf4  = (tid & 7) * 4;

    float acc[2][2][4];
#pragma unroll
    for (int am = 0; am < 2; am++)
#pragma unroll
        for (int an = 0; an < 2; an++)
#pragma unroll
            for (int j = 0; j < 4; j++) acc[am][an][j] = 0.f;

    int r4 = lane >> 2, q4 = lane & 3;

    {
#pragma unroll
        for (int i = 0; i < 2; i++) {
            int row = crow + i * 32;
            cp16((uint)__cvta_generic_to_shared(&Vs[0][row * LDP + cf4]),
                 V + (size_t)(c0 + row) * N + cf4);
            cp16((uint)__cvta_generic_to_shared(&Ps[0][row * LDP + cf4]),
                 P + (size_t)(n0 + row) * N + cf4);
        }
        asm volatile("cp.async.commit_group;");
    }

    for (int ch = 0; ch < NCHUNK; ch++) {
        int s = ch & 1;
        if (ch + 1 < NCHUNK) {
            int m1 = (ch + 1) * GBK;
#pragma unroll
            for (int i = 0; i < 2; i++) {
                int row = crow + i * 32;
                cp16((uint)__cvta_generic_to_shared(&Vs[s ^ 1][row * LDP + cf4]),
                     V + (size_t)(c0 + row) * N + m1 + cf4);
                cp16((uint)__cvta_generic_to_shared(&Ps[s ^ 1][row * LDP + cf4]),
                     P + (size_t)(n0 + row) * N + m1 + cf4);
            }
            asm volatile("cp.async.commit_group;");
            asm volatile("cp.async.wait_group 1;");
        } else {
            asm volatile("cp.async.wait_group 0;");
        }
        __syncthreads();

        const uint* Vss = Vs[s];
        const uint* Pss = Ps[s];
#pragma unroll
        for (int k8 = 0; k8 < GBK; k8 += 8) {
            uint a[2][4], bb[2][2];
#pragma unroll
            for (int am = 0; am < 2; am++) {
                int base = (wm + am * 16 + r4) * LDP + k8 + q4;
                a[am][0] = Vss[base];
                a[am][1] = Vss[base + 8 * LDP];
                a[am][2] = Vss[base + 4];
                a[am][3] = Vss[base + 8 * LDP + 4];
            }
#pragma unroll
            for (int an = 0; an < 2; an++) {
                int base = (wn + an * 8 + r4) * LDP + k8 + q4;
                bb[an][0] = Pss[base];
                bb[an][1] = Pss[base + 4];
            }
#pragma unroll
            for (int am = 0; am < 2; am++)
#pragma unroll
                for (int an = 0; an < 2; an++)
                    mma_tf32(acc[am][an], a[am], bb[an]);
        }
        __syncthreads();
    }

    float* O = g_out + (size_t)b * C * N;
    const float* RS = g_rsum + (size_t)b * N;
    int cc = (lane & 3) * 2;
    float inv[2][2];
#pragma unroll
    for (int an = 0; an < 2; an++) {
        int nc = n0 + wn + an * 8 + cc;
        inv[an][0] = 1.0f / RS[nc];
        inv[an][1] = 1.0f / RS[nc + 1];
    }
#pragma unroll
    for (int am = 0; am < 2; am++)
#pragma unroll
        for (int an = 0; an < 2; an++) {
            int cr = c0 + wm + am * 16 + r4;
            int ncol = n0 + wn + an * 8 + cc;
            float2 lo; lo.x = acc[am][an][0] * inv[an][0]; lo.y = acc[am][an][1] * inv[an][1];
            float2 hi; hi.x = acc[am][an][2] * inv[an][0]; hi.y = acc[am][an][3] * inv[an][1];
            *(float2*)(O + (size_t)cr * N + ncol)       = lo;
            *(float2*)(O + (size_t)(cr + 8) * N + ncol) = hi;
        }
}

// ---------------- kernel 5: nearest 8x upsample + residual ----------------
__global__ void upsample_add_kernel(const float* __restrict__ f, float* __restrict__ out) {
    size_t idx = (size_t)blockIdx.x * blockDim.x + threadIdx.x;  // over B*C*H*W/4
    int w4 = (int)(idx & 63);
    int h  = (int)((idx >> 6) & 255);
    size_t bc = idx >> 14;
    int hp = h >> 3;
    int wp = w4 >> 1;
    float s = g_out[bc * N + (size_t)hp * WP + wp];
    float4 a = ((const float4*)f)[idx];
    a.x += s; a.y += s; a.z += s; a.w += s;
    ((float4*)out)[idx] = a;
}

// ---------------- launch ----------------
extern "C" void kernel_launch(void* const* d_in, const int* in_sizes, int n_in,
                              void* d_out, int out_size) {
    const float* f  = (const float*)d_in[0];
    const float* qw = (const float*)d_in[1];
    const float* qb = (const float*)d_in[2];
    const float* kw = (const float*)d_in[3];
    const float* kb = (const float*)d_in[4];
    const float* vw = (const float*)d_in[5];
    const float* vb = (const float*)d_in[6];
    float* out = (float*)d_out;

    avgpool_kernel<<<(BATCH * C * N) / 256, 256>>>(f);
    qkv_mma_kernel<<<dim3(N / 64, 5, BATCH), 256>>>(qw, qb, kw, kb, vw, vb);
    attn_mma_kernel<<<dim3(N / 16, BATCH), 256>>>();
    out_gemm_kernel<<<dim3(N / GBN, C / GBM, BATCH), 256>>>();
    upsample_add_kernel<<<(BATCH * C * H * (W / 4)) / 256, 256>>>(f, out);
}